// round 16
// baseline (speedup 1.0000x reference)
#include <cuda_runtime.h>
#include <cuda_fp16.h>
#include <cstdint>

// FIR bandpass as banded-Toeplitz GEMM on mma.sync — fp16, 8-deep-M warps.
// R16: build_ext FUSED into the producer (LDG f32 -> cvt fp16 -> STS, warp-private).
//      Saves the 56us pre-kernel + g_ext round-trip; main kernel had DRAM headroom.
//
// out[t] = sum_j g[j] * xv[t-206+j],  g[j] = h[412-j]
// D[i,n] = sum_k A[i,k] * B[n,k],  A[i,k] = g[k-i]  (banded: 0 <= k-i <= 412)

#define T_LEN    30000
#define NROWS    2048
#define HALF     206
#define NCHUNK   9             // chunks of 64 samples (kb = 0..35; kb>33 folds away)
#define DMAX     26
#define NTHREADS 256
#define NT_I0    235           // ceil(30000/128)

#define AS_STRIDE 912          // 448 fp16 + 16B pad  (228 words ≡ 4 mod 32)
#define BS_STRIDE 144          // 64 fp16 + 16B pad   (36 words ≡ 4 mod 32)
#define OFF_AS   0             // 16 * 912 = 14592
#define OFF_B0   14592         // 2 buffers x 128*144 = 18432 each
#define OFF_B1   33024
#define SMEM_REQ 69632         // epilogue staging 128*136*4 dominates

__device__ __align__(16) char g_As[16 * AS_STRIDE];

__device__ __forceinline__ uint32_t smem_u32(const void* p) {
    return (uint32_t)__cvta_generic_to_shared(p);
}
__device__ __forceinline__ void ldx4(uint32_t r[4], uint32_t addr) {
    asm volatile("ldmatrix.sync.aligned.m8n8.x4.shared.b16 {%0,%1,%2,%3}, [%4];"
                 : "=r"(r[0]), "=r"(r[1]), "=r"(r[2]), "=r"(r[3]) : "r"(addr));
}
__device__ __forceinline__ void mma_f16(float c[4], const uint32_t a[4],
                                        const uint32_t b0, const uint32_t b1) {
    asm volatile(
        "mma.sync.aligned.m16n8k16.row.col.f32.f16.f16.f32 "
        "{%0,%1,%2,%3}, {%4,%5,%6,%7}, {%8,%9}, {%0,%1,%2,%3};"
        : "+f"(c[0]), "+f"(c[1]), "+f"(c[2]), "+f"(c[3])
        : "r"(a[0]), "r"(a[1]), "r"(a[2]), "r"(a[3]), "r"(b0), "r"(b1));
}

// ---------- pre-kernel: Toeplitz strip ----------
__global__ void build_as(const float* __restrict__ hcoef) {
    for (int idx = threadIdx.x; idx < 16 * 448; idx += 256) {
        const int r  = idx / 448;
        const int kq = idx - r * 448;
        const int j  = kq - r;
        const float gv = (j >= 0 && j <= 412) ? hcoef[412 - j] : 0.0f;
        *reinterpret_cast<__half*>(g_As + r * AS_STRIDE + 2 * kq) = __float2half_rn(gv);
    }
}

// ---------- main kernel ----------
__global__ void __launch_bounds__(NTHREADS, 2)
fir_mma(const float* __restrict__ x, float* __restrict__ out) {
    extern __shared__ char smem[];
    const uint32_t sb = smem_u32(smem);
    const int tid  = threadIdx.x;
    const int wid  = tid >> 5;           // 0..7 : rows [16*wid, 16*wid+16)
    const int lane = tid & 31;
    const int i0   = blockIdx.x;
    const int r0   = blockIdx.y * 128;

    // ---- copy Toeplitz strip to smem (block-wide) ----
    {
        const uint4* src = reinterpret_cast<const uint4*>(g_As);
        uint4* dst = reinterpret_cast<uint4*>(smem + OFF_AS);
        for (int i = tid; i < (16 * AS_STRIDE) / 16; i += NTHREADS) dst[i] = src[i];
    }

    // ---- producer: thread -> (row tid>>1, 32-sample segment) — WARP-PRIVATE ----
    const int prow = tid >> 1;           // rows 16*wid .. 16*wid+15 for this warp
    const int pseg = tid & 1;
    const float* __restrict__ xrow = x + (size_t)(r0 + prow) * T_LEN;
    const int mb0 = i0 * 128 - HALF + 32 * pseg;   // sample base for chunk 0
    char* const pbase = smem + (uint32_t)(prow * BS_STRIDE + pseg * 64);

    // load 16 samples starting at m0 (f32, reflect_limited at edges)
    auto ld16 = [&](int m0, float2 v[8]) {
        if (m0 >= 0 && m0 + 16 <= T_LEN) {
#pragma unroll
            for (int u = 0; u < 8; ++u)
                v[u] = *reinterpret_cast<const float2*>(xrow + m0 + 2 * u);
        } else {
            const float xf = xrow[0], xl = xrow[T_LEN - 1];
#pragma unroll
            for (int u = 0; u < 8; ++u) {
#pragma unroll
                for (int w = 0; w < 2; ++w) {
                    const int m = m0 + 2 * u + w;
                    float t;
                    if (m < 0)           t = 2.0f * xf - xrow[-m];
                    else if (m >= T_LEN) t = 2.0f * xl - xrow[2 * T_LEN - 2 - m];
                    else                 t = xrow[m];
                    (&v[u].x)[w] = t;
                }
            }
        }
    };
    // convert + store 16 samples (32B) at byte offset within this thread's slot
    auto st16 = [&](char* dst, const float2 v[8]) {
        uint32_t p[8];
#pragma unroll
        for (int u = 0; u < 8; ++u) {
            const __half2 h2 = __floats2half2_rn(v[u].x, v[u].y);
            p[u] = *reinterpret_cast<const uint32_t*>(&h2);
        }
        *reinterpret_cast<uint4*>(dst)      = make_uint4(p[0], p[1], p[2], p[3]);
        *reinterpret_cast<uint4*>(dst + 16) = make_uint4(p[4], p[5], p[6], p[7]);
    };

    // ---- consumer ldmatrix addresses (reads only this warp's 16 rows) ----
    const uint32_t as_base = sb + OFF_AS +
        (uint32_t)((lane & 15) * AS_STRIDE + ((lane >> 4) & 1) * 16);
    const uint32_t b_off = (uint32_t)((16 * wid + 8 * ((lane >> 4) & 1) + (lane & 7)) * BS_STRIDE
                                      + 16 * ((lane >> 3) & 1));

    float acc[8][2][4];
#pragma unroll
    for (int e = 0; e < 8; ++e)
#pragma unroll
        for (int s = 0; s < 2; ++s)
#pragma unroll
            for (int q = 0; q < 4; ++q) acc[e][s][q] = 0.0f;

    uint32_t af[8][4];                   // A-fragment ring (diag kb in slot kb&7)

    // prologue: produce chunk 0 into B0 (both 16-sample halves)
    {
        float2 v[8];
        ld16(mb0, v);       st16(pbase + OFF_B0, v);
        ld16(mb0 + 16, v);  st16(pbase + OFF_B0 + 32, v);
    }
    __syncthreads();                     // A strip visible; also orders B0

#pragma unroll
    for (int c = 0; c < NCHUNK; ++c) {
        const bool hn = (c + 1 < NCHUNK);
        float2 vs[8];
        if (hn) ld16(mb0 + 64 * (c + 1), vs);   // LDGs in flight during burst

        const uint32_t bbuf = sb + ((c & 1) ? OFF_B1 : OFF_B0) + b_off;

#pragma unroll
        for (int j = 0; j < 4; ++j) {
            const int kb = 4 * c + j;                      // compile-time
            if (kb <= DMAX)
                ldx4(af[kb & 7], as_base + (kb << 5));

            if (kb <= DMAX + 7) {                          // some e valid
                uint32_t bh[4];                            // nb0={0,1}, nb1={2,3}
                ldx4(bh, bbuf + (uint32_t)(32 * j));
#pragma unroll
                for (int e = 0; e < 8; ++e) {
                    if (kb - e >= 0 && kb - e <= DMAX) {
                        mma_f16(acc[e][0], af[(kb - e) & 7], bh[0], bh[1]);
                        mma_f16(acc[e][1], af[(kb - e) & 7], bh[2], bh[3]);
                    }
                }
            }
        }

        if (hn) {
            char* const nb = pbase + ((c & 1) ? OFF_B0 : OFF_B1);
            st16(nb, vs);                            // first half (was in flight)
            float2 v2[8];
            ld16(mb0 + 64 * (c + 1) + 16, v2);       // second half
            st16(nb + 32, v2);
        }
        __syncwarp();                    // warp-local visibility of next B tile
    }

    __syncthreads();                     // all warps done with A strip / B bufs

    // ---- epilogue: single-pass smem transpose -> coalesced stores ----
    float* S = reinterpret_cast<float*>(smem);    // S[n][t], stride 136 floats
#pragma unroll
    for (int e = 0; e < 8; ++e)
#pragma unroll
        for (int s = 0; s < 2; ++s) {
            const int tl = 16 * e + (lane >> 2);
            const int nl = 16 * wid + 8 * s + 2 * (lane & 3);
            S[nl * 136 + tl]           = acc[e][s][0];
            S[(nl + 1) * 136 + tl]     = acc[e][s][1];
            S[nl * 136 + tl + 8]       = acc[e][s][2];
            S[(nl + 1) * 136 + tl + 8] = acc[e][s][3];
        }
    __syncwarp();                        // staging rows are warp-private

    const int tg = i0 * 128 + 4 * lane;
    if (tg < T_LEN) {
#pragma unroll
        for (int rr = 0; rr < 16; ++rr) {
            const int n = wid * 16 + rr;
            const float4 v = *reinterpret_cast<const float4*>(&S[n * 136 + 4 * lane]);
            *reinterpret_cast<float4*>(&out[(size_t)(r0 + n) * T_LEN + tg]) = v;
        }
    }
}

extern "C" void kernel_launch(void* const* d_in, const int* in_sizes, int n_in,
                              void* d_out, int out_size) {
    const float* x = (const float*)d_in[0];   // (32, 64, 30000) f32
    const float* h = (const float*)d_in[1];   // (413,) f32
    float* out = (float*)d_out;

    cudaFuncSetAttribute(fir_mma,
                         cudaFuncAttributeMaxDynamicSharedMemorySize, SMEM_REQ);

    build_as<<<1, 256>>>(h);

    dim3 grid(NT_I0, NROWS / 128);
    fir_mma<<<grid, NTHREADS, SMEM_REQ>>>(x, out);
}

// round 17
// speedup vs baseline: 1.0985x; 1.0985x over previous
#include <cuda_runtime.h>
#include <cuda_fp16.h>
#include <cstdint>

// FIR bandpass as banded-Toeplitz GEMM on mma.sync — fp16, 8-deep-M warps.
// R17: fused producer, spill-proof: 8-sample pieces with ~8-reg live ranges
//      (R16 spilled at regs=128 by holding 32 staging regs across the burst).
//      Warp-private B double buffer, no pre-extension kernel, no g_ext traffic.
//
// out[t] = sum_j g[j] * xv[t-206+j],  g[j] = h[412-j]
// D[i,n] = sum_k A[i,k] * B[n,k],  A[i,k] = g[k-i]  (banded: 0 <= k-i <= 412)

#define T_LEN    30000
#define NROWS    2048
#define HALF     206
#define NCHUNK   9             // chunks of 64 samples (kb = 0..35; kb>33 folds away)
#define DMAX     26
#define NTHREADS 256
#define NT_I0    235           // ceil(30000/128)

#define AS_STRIDE 912          // 448 fp16 + 16B pad  (228 words ≡ 4 mod 32)
#define BS_STRIDE 144          // 64 fp16 + 16B pad   (36 words ≡ 4 mod 32)
#define OFF_AS   0             // 16 * 912 = 14592
#define OFF_B0   14592         // 2 buffers x 128*144 = 18432 each
#define OFF_B1   33024
#define SMEM_REQ 69632         // epilogue staging 128*136*4 dominates

__device__ __align__(16) char g_As[16 * AS_STRIDE];

__device__ __forceinline__ uint32_t smem_u32(const void* p) {
    return (uint32_t)__cvta_generic_to_shared(p);
}
__device__ __forceinline__ void ldx4(uint32_t r[4], uint32_t addr) {
    asm volatile("ldmatrix.sync.aligned.m8n8.x4.shared.b16 {%0,%1,%2,%3}, [%4];"
                 : "=r"(r[0]), "=r"(r[1]), "=r"(r[2]), "=r"(r[3]) : "r"(addr));
}
__device__ __forceinline__ void mma_f16(float c[4], const uint32_t a[4],
                                        const uint32_t b0, const uint32_t b1) {
    asm volatile(
        "mma.sync.aligned.m16n8k16.row.col.f32.f16.f16.f32 "
        "{%0,%1,%2,%3}, {%4,%5,%6,%7}, {%8,%9}, {%0,%1,%2,%3};"
        : "+f"(c[0]), "+f"(c[1]), "+f"(c[2]), "+f"(c[3])
        : "r"(a[0]), "r"(a[1]), "r"(a[2]), "r"(a[3]), "r"(b0), "r"(b1));
}

// load 8 samples (even m0) with reflect_limited edges — 8 live regs
__device__ __forceinline__ void ld8(const float* __restrict__ xrow, int m0,
                                    float2 v[4]) {
    if (m0 >= 0 && m0 + 8 <= T_LEN) {
#pragma unroll
        for (int u = 0; u < 4; ++u)
            v[u] = *reinterpret_cast<const float2*>(xrow + m0 + 2 * u);
    } else {
        const float xf = xrow[0], xl = xrow[T_LEN - 1];
#pragma unroll
        for (int u = 0; u < 4; ++u) {
#pragma unroll
            for (int w = 0; w < 2; ++w) {
                const int m = m0 + 2 * u + w;
                float t;
                if (m < 0)           t = 2.0f * xf - xrow[-m];
                else if (m >= T_LEN) t = 2.0f * xl - xrow[2 * T_LEN - 2 - m];
                else                 t = xrow[m];
                (&v[u].x)[w] = t;
            }
        }
    }
}
// convert + store 8 samples as one 16B STS
__device__ __forceinline__ void st8(char* dst, const float2 v[4]) {
    uint32_t p[4];
#pragma unroll
    for (int u = 0; u < 4; ++u) {
        const __half2 h2 = __floats2half2_rn(v[u].x, v[u].y);
        p[u] = *reinterpret_cast<const uint32_t*>(&h2);
    }
    *reinterpret_cast<uint4*>(dst) = make_uint4(p[0], p[1], p[2], p[3]);
}

// ---------- pre-kernel: Toeplitz strip ----------
__global__ void build_as(const float* __restrict__ hcoef) {
    for (int idx = threadIdx.x; idx < 16 * 448; idx += 256) {
        const int r  = idx / 448;
        const int kq = idx - r * 448;
        const int j  = kq - r;
        const float gv = (j >= 0 && j <= 412) ? hcoef[412 - j] : 0.0f;
        *reinterpret_cast<__half*>(g_As + r * AS_STRIDE + 2 * kq) = __float2half_rn(gv);
    }
}

// ---------- main kernel ----------
__global__ void __launch_bounds__(NTHREADS, 2)
fir_mma(const float* __restrict__ x, float* __restrict__ out) {
    extern __shared__ char smem[];
    const uint32_t sb = smem_u32(smem);
    const int tid  = threadIdx.x;
    const int wid  = tid >> 5;           // 0..7 : rows [16*wid, 16*wid+16)
    const int lane = tid & 31;
    const int i0   = blockIdx.x;
    const int r0   = blockIdx.y * 128;

    // ---- copy Toeplitz strip to smem (block-wide) ----
    {
        const uint4* src = reinterpret_cast<const uint4*>(g_As);
        uint4* dst = reinterpret_cast<uint4*>(smem + OFF_AS);
        for (int i = tid; i < (16 * AS_STRIDE) / 16; i += NTHREADS) dst[i] = src[i];
    }

    // ---- producer: thread -> (row tid>>1, 32-sample segment) — WARP-PRIVATE ----
    const int prow = tid >> 1;           // rows 16*wid .. 16*wid+15 for this warp
    const int pseg = tid & 1;
    const float* __restrict__ xrow = x + (size_t)(r0 + prow) * T_LEN;
    const int mb0 = i0 * 128 - HALF + 32 * pseg;   // thread's chunk-0 base (even)
    char* const pbase = smem + (uint32_t)(prow * BS_STRIDE + pseg * 64);

    // ---- consumer ldmatrix addresses (reads only this warp's 16 rows) ----
    const uint32_t as_base = sb + OFF_AS +
        (uint32_t)((lane & 15) * AS_STRIDE + ((lane >> 4) & 1) * 16);
    const uint32_t b_off = (uint32_t)((16 * wid + 8 * ((lane >> 4) & 1) + (lane & 7)) * BS_STRIDE
                                      + 16 * ((lane >> 3) & 1));

    float acc[8][2][4];
#pragma unroll
    for (int e = 0; e < 8; ++e)
#pragma unroll
        for (int s = 0; s < 2; ++s)
#pragma unroll
            for (int q = 0; q < 4; ++q) acc[e][s][q] = 0.0f;

    uint32_t af[8][4];                   // A-fragment ring (diag kb in slot kb&7)

    // prologue: produce chunk 0 into B0 (4 pieces, short live ranges)
    {
        float2 v[4];
        ld8(xrow, mb0,      v); st8(pbase + OFF_B0,      v);
        ld8(xrow, mb0 +  8, v); st8(pbase + OFF_B0 + 16, v);
        ld8(xrow, mb0 + 16, v); st8(pbase + OFF_B0 + 32, v);
        ld8(xrow, mb0 + 24, v); st8(pbase + OFF_B0 + 48, v);
    }
    __syncthreads();                     // A strip + B0 visible

#pragma unroll
    for (int c = 0; c < NCHUNK; ++c) {
        const bool hn = (c + 1 < NCHUNK);
        const int mnext = mb0 + 64 * (c + 1);
        float2 v0[4];
        if (hn) ld8(xrow, mnext, v0);    // piece 0 in flight during the burst

        const uint32_t bbuf = sb + ((c & 1) ? OFF_B1 : OFF_B0) + b_off;

#pragma unroll
        for (int j = 0; j < 4; ++j) {
            const int kb = 4 * c + j;                      // compile-time
            if (kb <= DMAX)
                ldx4(af[kb & 7], as_base + (kb << 5));

            if (kb <= DMAX + 7) {                          // some e valid
                uint32_t bh[4];                            // nb0={0,1}, nb1={2,3}
                ldx4(bh, bbuf + (uint32_t)(32 * j));
#pragma unroll
                for (int e = 0; e < 8; ++e) {
                    if (kb - e >= 0 && kb - e <= DMAX) {
                        mma_f16(acc[e][0], af[(kb - e) & 7], bh[0], bh[1]);
                        mma_f16(acc[e][1], af[(kb - e) & 7], bh[2], bh[3]);
                    }
                }
            }
        }

        if (hn) {                         // pieces for chunk c+1, 8-reg live ranges
            char* const nb = pbase + ((c & 1) ? OFF_B0 : OFF_B1);
            st8(nb, v0);
            float2 v[4];
            ld8(xrow, mnext +  8, v); st8(nb + 16, v);
            ld8(xrow, mnext + 16, v); st8(nb + 32, v);
            ld8(xrow, mnext + 24, v); st8(nb + 48, v);
        }
        __syncwarp();                    // warp-local visibility of next B tile
    }

    __syncthreads();                     // all warps done with A strip / B bufs

    // ---- epilogue: single-pass smem transpose -> coalesced stores ----
    float* S = reinterpret_cast<float*>(smem);    // S[n][t], stride 136 floats
#pragma unroll
    for (int e = 0; e < 8; ++e)
#pragma unroll
        for (int s = 0; s < 2; ++s) {
            const int tl = 16 * e + (lane >> 2);
            const int nl = 16 * wid + 8 * s + 2 * (lane & 3);
            S[nl * 136 + tl]           = acc[e][s][0];
            S[(nl + 1) * 136 + tl]     = acc[e][s][1];
            S[nl * 136 + tl + 8]       = acc[e][s][2];
            S[(nl + 1) * 136 + tl + 8] = acc[e][s][3];
        }
    __syncwarp();                        // staging rows are warp-private

    const int tg = i0 * 128 + 4 * lane;
    if (tg < T_LEN) {
#pragma unroll
        for (int rr = 0; rr < 16; ++rr) {
            const int n = wid * 16 + rr;
            const float4 v = *reinterpret_cast<const float4*>(&S[n * 136 + 4 * lane]);
            *reinterpret_cast<float4*>(&out[(size_t)(r0 + n) * T_LEN + tg]) = v;
        }
    }
}

extern "C" void kernel_launch(void* const* d_in, const int* in_sizes, int n_in,
                              void* d_out, int out_size) {
    const float* x = (const float*)d_in[0];   // (32, 64, 30000) f32
    const float* h = (const float*)d_in[1];   // (413,) f32
    float* out = (float*)d_out;

    cudaFuncSetAttribute(fir_mma,
                         cudaFuncAttributeMaxDynamicSharedMemorySize, SMEM_REQ);

    build_as<<<1, 256>>>(h);

    dim3 grid(NT_I0, NROWS / 128);
    fir_mma<<<grid, NTHREADS, SMEM_REQ>>>(x, out);
}